// round 9
// baseline (speedup 1.0000x reference)
#include <cuda_runtime.h>
#include <math.h>

typedef unsigned long long ull;

// ---- scratch (device globals; referenced ONLY inside device code) ----------
#define NMAX 100000
#define EMAX 1600000
__device__ __align__(16) float g_H[NMAX * 128];    // GEMM output (dense H)
__device__ __align__(16) float g_AG[NMAX * 128];   // aggregation result
__device__ float  g_dinv[NMAX];                    // rsqrt(weighted degree)
__device__ int    g_cnt[NMAX];                     // in-degree counts
__device__ int    g_rowptr[NMAX + 1];              // CSR row pointers (by dst)
__device__ int    g_pos[NMAX];                     // scatter cursors
__device__ __align__(8) float2 g_edge[EMAX];       // {src_bits, coeff} by dst
__device__ int    g_is64;                          // edge_index is int64?

// ---- packed fp32x2 helpers (FFMA2: 2x fp32 FMA throughput) -----------------
__device__ __forceinline__ ull ffma2(ull a, ull b, ull c) {
    ull d;
    asm("fma.rn.f32x2 %0, %1, %2, %3;" : "=l"(d) : "l"(a), "l"(b), "l"(c));
    return d;
}
__device__ __forceinline__ float2 unpack2(ull v) {
    float2 r;
    asm("mov.b64 {%0, %1}, %2;" : "=f"(r.x), "=f"(r.y) : "l"(v));
    return r;
}

// ---- edge-index dtype detection --------------------------------------------
__global__ void detect_kernel(const int* ei32, int twoE) {
    __shared__ int any;
    if (threadIdx.x == 0) any = 0;
    __syncthreads();
    int lim = twoE < 8192 ? twoE : 8192;
    for (int i = threadIdx.x * 2 + 1; i < lim; i += 512)
        if (ei32[i] != 0) any = 1;
    __syncthreads();
    if (threadIdx.x == 0) g_is64 = (any == 0) ? 1 : 0;
}

__device__ __forceinline__ void load_edge(const void* ei, int E, int e,
                                          int& r, int& c) {
    if (g_is64) {
        const long long* p = (const long long*)ei;
        r = (int)p[e];
        c = (int)p[(size_t)E + e];
    } else {
        const int* p = (const int*)ei;
        r = p[e];
        c = p[(size_t)E + e];
    }
}

// ---- degree + histogram ------------------------------------------------------
__global__ void deg_init_kernel(int n) {
    int i = blockIdx.x * blockDim.x + threadIdx.x;
    if (i < n) { g_dinv[i] = 1.0f; g_cnt[i] = 0; }   // self-loop weight = 1
}

__global__ void deg_accum_kernel(const void* ei, const float* w, int E) {
    int e = blockIdx.x * blockDim.x + threadIdx.x;
    if (e < E) {
        int r, c;
        load_edge(ei, E, e, r, c);
        atomicAdd(&g_dinv[c], w[e]);
        atomicAdd(&g_cnt[c], 1);
    }
}

__global__ void deg_fin_kernel(int n) {
    int i = blockIdx.x * blockDim.x + threadIdx.x;
    if (i < n) {
        float d = g_dinv[i];                 // deg >= 1 always
        float r = rsqrtf(d);
        r = r * (1.5f - 0.5f * d * r * r);   // Newton step: sub-ulp rsqrt
        g_dinv[i] = r;
    }
}

// ---- single-block exclusive scan of g_cnt -> g_rowptr, g_pos ----------------
__global__ __launch_bounds__(1024)
void scan_kernel(int n) {
    __shared__ int bsum[1024];
    int t = threadIdx.x;
    int chunk = (n + 1023) / 1024;
    int s = t * chunk;
    int e = min(s + chunk, n);
    int sum = 0;
    for (int i = s; i < e; i++) sum += g_cnt[i];
    bsum[t] = sum;
    __syncthreads();
    for (int off = 1; off < 1024; off <<= 1) {
        int v = 0;
        if (t >= off) v = bsum[t - off];
        __syncthreads();
        if (t >= off) bsum[t] += v;
        __syncthreads();
    }
    int run = (t == 0) ? 0 : bsum[t - 1];
    for (int i = s; i < e; i++) {
        g_rowptr[i] = run;
        g_pos[i] = run;
        run += g_cnt[i];
    }
    if (t == 1023 || e == n) g_rowptr[n] = bsum[1023];
}

// ---- scatter edges into CSR, precompute coeff = dinv_r * w * dinv_c ---------
__global__ void scatter_kernel(const void* ei, const float* w, int E) {
    int e = blockIdx.x * blockDim.x + threadIdx.x;
    if (e >= E) return;
    int r, c;
    load_edge(ei, E, e, r, c);
    float coeff = g_dinv[r] * __ldg(&w[e]) * g_dinv[c];
    int p = atomicAdd(&g_pos[c], 1);
    g_edge[p] = make_float2(__int_as_float(r), coeff);
}

// ---- GEMM (FFMA2, k-pair packed): OUT = f(X)[N,128] @ W[128,MCOLS] ---------
// acc[col][node] = {sum over even k, sum over odd k}; folded in epilogue.
// X tile node-major (conflict-free); W tile pair-major float2 wsp[k/2][c] =
// {W[k][c], W[k+1][c]} (conflict-free STS.64 build, coalesced LDG).
// XSEL: 0 = Xarg, 1 = g_AG.   OUTSEL: 0 = OUTarg(d_out), 1 = g_H.
template <int MCOLS, int XSEL, int OUTSEL, bool IN_RELU, bool OUT_SIG>
__global__ __launch_bounds__(256)
void gemm_kernel(const float* Xarg, const float* W,
                 const float* in_bias, const float* out_bias,
                 float* OUTarg, int n) {
    constexpr int BN = 64;            // nodes per block
    constexpr int BK = 64;            // K chunk
    constexpr int CG = MCOLS / 4;     // col groups (4 cols each): 32 or 16
    constexpr int NG = 256 / CG;      // node groups: 8 or 16
    constexpr int NPT = BN / NG;      // nodes per thread: 8 or 4

    const float* X = (XSEL == 0) ? Xarg : g_AG;
    float* OUT = (OUTSEL == 0) ? OUTarg : g_H;

    __shared__ __align__(16) float2 wsp[(BK / 2) * MCOLS];  // k-pair major W
    __shared__ __align__(16) float xs[BN * BK];             // node-major X

    const int tid = threadIdx.x;
    const int cg = tid % CG;
    const int ng = tid / CG;
    const int node0 = blockIdx.x * BN;

    ull acc[4][NPT];
#pragma unroll
    for (int c = 0; c < 4; c++)
#pragma unroll
        for (int p = 0; p < NPT; p++) acc[c][p] = 0ull;

    for (int kt = 0; kt < 128; kt += BK) {
        // build W pair tile: lanes cover consecutive c at fixed k-pair
        // -> two coalesced 128B LDGs + conflict-free STS.64
#pragma unroll
        for (int i = tid; i < (BK / 2) * MCOLS; i += 256) {
            int k2 = i / MCOLS;
            int c = i % MCOLS;
            float a = W[(size_t)(kt + 2 * k2) * MCOLS + c];
            float b = W[(size_t)(kt + 2 * k2 + 1) * MCOLS + c];
            wsp[i] = make_float2(a, b);
        }
        // load X chunk (coalesced float4), optional relu(x+b), node-major
#pragma unroll
        for (int i = tid; i < BN * BK / 4; i += 256) {
            int flat = i * 4;
            int nn = flat / BK;
            int kk = flat % BK;
            float4 v = make_float4(0.f, 0.f, 0.f, 0.f);
            int gn = node0 + nn;
            if (gn < n) {
                v = *(const float4*)(X + (size_t)gn * 128 + kt + kk);
                if (IN_RELU) {
                    float4 bb = *(const float4*)(in_bias + kt + kk);
                    v.x = fmaxf(v.x + bb.x, 0.f);
                    v.y = fmaxf(v.y + bb.y, 0.f);
                    v.z = fmaxf(v.z + bb.z, 0.f);
                    v.w = fmaxf(v.w + bb.w, 0.f);
                }
            }
            *(float4*)(xs + nn * BK + kk) = v;
        }
        __syncthreads();

#pragma unroll 4
        for (int k4 = 0; k4 < BK; k4 += 4) {
            // W pairs for 4 columns x 2 k-pairs (two LDS.128 per k-pair)
            const ull* wp0 = (const ull*)(wsp + (k4 / 2) * MCOLS + cg * 4);
            const ull* wp1 = (const ull*)(wsp + (k4 / 2 + 1) * MCOLS + cg * 4);
            ull wa0 = wp0[0], wa1 = wp0[1], wa2 = wp0[2], wa3 = wp0[3];
            ull wb0 = wp1[0], wb1 = wp1[1], wb2 = wp1[2], wb3 = wp1[3];
#pragma unroll
            for (int j = 0; j < NPT; j++) {
                // two packed k-pairs for this node (broadcast LDS.128)
                ulonglong2 xv =
                    *(const ulonglong2*)(xs + (ng * NPT + j) * BK + k4);
                acc[0][j] = ffma2(xv.x, wa0, acc[0][j]);
                acc[1][j] = ffma2(xv.x, wa1, acc[1][j]);
                acc[2][j] = ffma2(xv.x, wa2, acc[2][j]);
                acc[3][j] = ffma2(xv.x, wa3, acc[3][j]);
                acc[0][j] = ffma2(xv.y, wb0, acc[0][j]);
                acc[1][j] = ffma2(xv.y, wb1, acc[1][j]);
                acc[2][j] = ffma2(xv.y, wb2, acc[2][j]);
                acc[3][j] = ffma2(xv.y, wb3, acc[3][j]);
            }
        }
        __syncthreads();
    }

    // epilogue: fold k-pair partials, optional sigmoid, store float4
#pragma unroll
    for (int j = 0; j < NPT; j++) {
        int gn = node0 + ng * NPT + j;
        if (gn >= n) continue;
        float2 s0 = unpack2(acc[0][j]);
        float2 s1 = unpack2(acc[1][j]);
        float2 s2 = unpack2(acc[2][j]);
        float2 s3 = unpack2(acc[3][j]);
        float4 r = make_float4(s0.x + s0.y, s1.x + s1.y,
                               s2.x + s2.y, s3.x + s3.y);
        if (OUT_SIG) {
            float4 bb = *(const float4*)(out_bias + cg * 4);
            r.x = 1.f / (1.f + expf(-(r.x + bb.x)));
            r.y = 1.f / (1.f + expf(-(r.y + bb.y)));
            r.z = 1.f / (1.f + expf(-(r.z + bb.z)));
            r.w = 1.f / (1.f + expf(-(r.w + bb.w)));
        }
        *(float4*)(OUT + (size_t)gn * MCOLS + cg * 4) = r;
    }
}

// ---- CSR aggregation: g_AG[n] = dinv[n]^2*g_H[n] + sum_e coeff_e*g_H[src_e]
__global__ __launch_bounds__(256)
void agg_csr_kernel(int n) {
    int gid = blockIdx.x * blockDim.x + threadIdx.x;
    int node = gid >> 5;
    if (node >= n) return;
    int lane = gid & 31;

    int beg = g_rowptr[node];
    int end = g_rowptr[node + 1];

    float d = g_dinv[node];
    float s = d * d;
    float4 acc = *(const float4*)(g_H + (size_t)node * 128 + lane * 4);
    acc.x *= s; acc.y *= s; acc.z *= s; acc.w *= s;

    int j = beg;
    for (; j + 1 < end; j += 2) {
        float2 e0 = g_edge[j];
        float2 e1 = g_edge[j + 1];
        int s0 = __float_as_int(e0.x);
        int s1 = __float_as_int(e1.x);
        float4 v0 = *(const float4*)(g_H + (size_t)s0 * 128 + lane * 4);
        float4 v1 = *(const float4*)(g_H + (size_t)s1 * 128 + lane * 4);
        acc.x = fmaf(e0.y, v0.x, acc.x);
        acc.y = fmaf(e0.y, v0.y, acc.y);
        acc.z = fmaf(e0.y, v0.z, acc.z);
        acc.w = fmaf(e0.y, v0.w, acc.w);
        acc.x = fmaf(e1.y, v1.x, acc.x);
        acc.y = fmaf(e1.y, v1.y, acc.y);
        acc.z = fmaf(e1.y, v1.z, acc.z);
        acc.w = fmaf(e1.y, v1.w, acc.w);
    }
    if (j < end) {
        float2 e0 = g_edge[j];
        int s0 = __float_as_int(e0.x);
        float4 v0 = *(const float4*)(g_H + (size_t)s0 * 128 + lane * 4);
        acc.x = fmaf(e0.y, v0.x, acc.x);
        acc.y = fmaf(e0.y, v0.y, acc.y);
        acc.z = fmaf(e0.y, v0.z, acc.z);
        acc.w = fmaf(e0.y, v0.w, acc.w);
    }

    *(float4*)(g_AG + (size_t)node * 128 + lane * 4) = acc;
}

// ---- launch -------------------------------------------------------------------
extern "C" void kernel_launch(void* const* d_in, const int* in_sizes, int n_in,
                              void* d_out, int out_size) {
    const float* x   = (const float*)d_in[0];
    const void*  ei  = d_in[1];
    const float* ew  = (const float*)d_in[2];
    const float* W1  = (const float*)d_in[3];
    const float* b1  = (const float*)d_in[4];
    const float* W2  = (const float*)d_in[5];
    const float* b2  = (const float*)d_in[6];
    const float* Wfc = (const float*)d_in[7];
    const float* bfc = (const float*)d_in[8];

    int N = in_sizes[0] / 128;
    int E = in_sizes[2];

    int gb = (N + 63) / 64;
    int awarps = (N * 32 + 255) / 256;
    int eb = (E + 255) / 256;
    int nb = (N + 255) / 256;

    // fork a side stream: CSR build runs concurrently with layer-1 GEMM.
    cudaStream_t s2;
    cudaStreamCreateWithFlags(&s2, cudaStreamNonBlocking);
    cudaEvent_t evF, evJ;
    cudaEventCreateWithFlags(&evF, cudaEventDisableTiming);
    cudaEventCreateWithFlags(&evJ, cudaEventDisableTiming);

    cudaEventRecord(evF, 0);
    cudaStreamWaitEvent(s2, evF, 0);

    // side stream: edge dtype detect, degrees, CSR build (coeff precomputed)
    detect_kernel<<<1, 256, 0, s2>>>((const int*)ei, 2 * E);
    deg_init_kernel<<<nb, 256, 0, s2>>>(N);
    deg_accum_kernel<<<eb, 256, 0, s2>>>(ei, ew, E);
    deg_fin_kernel<<<nb, 256, 0, s2>>>(N);
    scan_kernel<<<1, 1024, 0, s2>>>(N);
    scatter_kernel<<<eb, 256, 0, s2>>>(ei, ew, E);
    cudaEventRecord(evJ, s2);

    // main stream: layer-1 GEMM overlaps the build
    gemm_kernel<128, 0, 1, false, false><<<gb, 256>>>(x, W1, nullptr,
                                                      nullptr, nullptr, N);
    cudaStreamWaitEvent(0, evJ, 0);

    // layer 1 aggregation
    agg_csr_kernel<<<awarps, 256>>>(N);

    // layer 2: g_H = relu(g_AG + b1)@W2;  g_AG = self + CSR-gather
    gemm_kernel<128, 1, 1, true, false><<<gb, 256>>>(nullptr, W2, b1,
                                                     nullptr, nullptr, N);
    agg_csr_kernel<<<awarps, 256>>>(N);

    // final: d_out = sigmoid( relu(g_AG + b2) @ Wfc + bfc )
    gemm_kernel<64, 1, 0, true, true><<<gb, 256>>>(nullptr, Wfc, b2, bfc,
                                                   (float*)d_out, N);
}

// round 11
// speedup vs baseline: 1.2026x; 1.2026x over previous
#include <cuda_runtime.h>
#include <math.h>
#include <stdint.h>

typedef unsigned long long ull;

// ---- scratch (device globals; referenced ONLY inside device code) ----------
#define NMAX 100000
#define NPAD 100096              /* 782 * 128 (mma tile padding) */
#define EMAX 1600000
__device__ __align__(16) float g_H[NPAD * 128];    // GEMM output (dense H)
__device__ __align__(16) float g_AG[NPAD * 128];   // aggregation result
__device__ float  g_dinv[NMAX];                    // rsqrt(weighted degree)
__device__ int    g_cnt[NMAX];                     // in-degree counts
__device__ int    g_rowptr[NMAX + 1];              // CSR row pointers (by dst)
__device__ int    g_pos[NMAX];                     // scatter cursors
__device__ __align__(8) float2 g_edge[EMAX];       // {src_bits, coeff} by dst
__device__ int    g_is64;                          // edge_index is int64?

// ---- tf32 conversion + warp mma (plain sm_103-legal, sm_80+ PTX) -----------
__device__ __forceinline__ uint32_t f2tf(float x) {
    uint32_t r;
    asm("cvt.rna.tf32.f32 %0, %1;" : "=r"(r) : "f"(x));
    return r;
}
__device__ __forceinline__ void mma8(float* d, const uint32_t* a,
                                     const uint32_t* b) {
    asm volatile(
        "mma.sync.aligned.m16n8k8.row.col.f32.tf32.tf32.f32 "
        "{%0,%1,%2,%3}, {%4,%5,%6,%7}, {%8,%9}, {%0,%1,%2,%3};"
        : "+f"(d[0]), "+f"(d[1]), "+f"(d[2]), "+f"(d[3])
        : "r"(a[0]), "r"(a[1]), "r"(a[2]), "r"(a[3]), "r"(b[0]), "r"(b[1]));
}

// ---- edge-index dtype detection --------------------------------------------
__global__ void detect_kernel(const int* ei32, int twoE) {
    __shared__ int any;
    if (threadIdx.x == 0) any = 0;
    __syncthreads();
    int lim = twoE < 8192 ? twoE : 8192;
    for (int i = threadIdx.x * 2 + 1; i < lim; i += 512)
        if (ei32[i] != 0) any = 1;
    __syncthreads();
    if (threadIdx.x == 0) g_is64 = (any == 0) ? 1 : 0;
}

__device__ __forceinline__ void load_edge(const void* ei, int E, int e,
                                          int& r, int& c) {
    if (g_is64) {
        const long long* p = (const long long*)ei;
        r = (int)p[e];
        c = (int)p[(size_t)E + e];
    } else {
        const int* p = (const int*)ei;
        r = p[e];
        c = p[(size_t)E + e];
    }
}

// ---- degree + histogram ------------------------------------------------------
__global__ void deg_init_kernel(int n) {
    int i = blockIdx.x * blockDim.x + threadIdx.x;
    if (i < n) { g_dinv[i] = 1.0f; g_cnt[i] = 0; }
}

__global__ void deg_accum_kernel(const void* ei, const float* w, int E) {
    int e = blockIdx.x * blockDim.x + threadIdx.x;
    if (e < E) {
        int r, c;
        load_edge(ei, E, e, r, c);
        atomicAdd(&g_dinv[c], w[e]);
        atomicAdd(&g_cnt[c], 1);
    }
}

__global__ void deg_fin_kernel(int n) {
    int i = blockIdx.x * blockDim.x + threadIdx.x;
    if (i < n) {
        float d = g_dinv[i];
        float r = rsqrtf(d);
        r = r * (1.5f - 0.5f * d * r * r);
        g_dinv[i] = r;
    }
}

// ---- single-block exclusive scan of g_cnt -> g_rowptr, g_pos ----------------
__global__ __launch_bounds__(1024)
void scan_kernel(int n) {
    __shared__ int bsum[1024];
    int t = threadIdx.x;
    int chunk = (n + 1023) / 1024;
    int s = t * chunk;
    int e = min(s + chunk, n);
    int sum = 0;
    for (int i = s; i < e; i++) sum += g_cnt[i];
    bsum[t] = sum;
    __syncthreads();
    for (int off = 1; off < 1024; off <<= 1) {
        int v = 0;
        if (t >= off) v = bsum[t - off];
        __syncthreads();
        if (t >= off) bsum[t] += v;
        __syncthreads();
    }
    int run = (t == 0) ? 0 : bsum[t - 1];
    for (int i = s; i < e; i++) {
        g_rowptr[i] = run;
        g_pos[i] = run;
        run += g_cnt[i];
    }
    if (t == 1023 || e == n) g_rowptr[n] = bsum[1023];
}

// ---- scatter edges into CSR, precompute coeff --------------------------------
__global__ void scatter_kernel(const void* ei, const float* w, int E) {
    int e = blockIdx.x * blockDim.x + threadIdx.x;
    if (e >= E) return;
    int r, c;
    load_edge(ei, E, e, r, c);
    float coeff = g_dinv[r] * __ldg(&w[e]) * g_dinv[c];
    int p = atomicAdd(&g_pos[c], 1);
    g_edge[p] = make_float2(__int_as_float(r), coeff);
}

// ==== warp-MMA tf32 GEMM: g_H[128-tile] = f(X)[128,128] @ W[128,128] ========
// block 256 thr / 8 warps; warp tile 32(M)x64(N); m16n8k8 fragments.
// X tile row-major (xs[row][k], LD=132, conflict-free A loads),
// W tile n-major   (ws[col][k], LD=132, conflict-free B loads).
// XSEL: 0 = Xarg, 1 = g_AG.   IN_RELU: relu(X + in_bias) on load.
template <int XSEL, bool IN_RELU>
__global__ __launch_bounds__(256, 1)
void mma_gemm_kernel(const float* Xarg, const float* W,
                     const float* in_bias, int n) {
    constexpr int LD = 132;
    extern __shared__ __align__(16) uint32_t smem[];
    uint32_t* xs = smem;               // [128][LD]
    uint32_t* ws = smem + 128 * LD;    // [128 cols][LD k]

    const float* X = (XSEL == 0) ? Xarg : g_AG;

    const int tid = threadIdx.x;
    const int node0 = blockIdx.x * 128;

    // stage X tile (coalesced float4, relu+bias fused, tf32-converted)
    for (int i = tid; i < 128 * 32; i += 256) {
        int row = i >> 5;
        int k4 = (i & 31) * 4;
        float4 v = make_float4(0.f, 0.f, 0.f, 0.f);
        int gn = node0 + row;
        if (gn < n) {
            v = *(const float4*)(X + (size_t)gn * 128 + k4);
            if (IN_RELU) {
                float4 bb = *(const float4*)(in_bias + k4);
                v.x = fmaxf(v.x + bb.x, 0.f);
                v.y = fmaxf(v.y + bb.y, 0.f);
                v.z = fmaxf(v.z + bb.z, 0.f);
                v.w = fmaxf(v.w + bb.w, 0.f);
            }
        }
        uint4 t = make_uint4(f2tf(v.x), f2tf(v.y), f2tf(v.z), f2tf(v.w));
        *(uint4*)(xs + row * LD + k4) = t;
    }
    // stage W transposed to n-major: ws[c][k] = W[k][c]
    // i -> (k-quad, col): LDG coalesced over col; 4 scattered STS each
    for (int i = tid; i < 32 * 128; i += 256) {
        int kq = i >> 7;         // 0..31 (k in groups of 4)
        int c = i & 127;
#pragma unroll
        for (int j = 0; j < 4; j++) {
            int k = kq * 4 + j;
            ws[c * LD + k] = f2tf(W[(size_t)k * 128 + c]);
        }
    }
    __syncthreads();

    const int wid = tid >> 5;
    const int lane = tid & 31;
    const int g = lane >> 2;     // groupID (0..7)
    const int q = lane & 3;      // threadID_in_group (0..3)
    const int wm = wid & 3;      // warp M index: rows wm*32..+31
    const int wn = wid >> 2;     // warp N index: cols wn*64..+63

    float acc[2][8][4];
#pragma unroll
    for (int mt = 0; mt < 2; mt++)
#pragma unroll
        for (int nt = 0; nt < 8; nt++)
#pragma unroll
            for (int r = 0; r < 4; r++) acc[mt][nt][r] = 0.f;

#pragma unroll 4
    for (int k0 = 0; k0 < 128; k0 += 8) {
        uint32_t a[2][4];
#pragma unroll
        for (int mt = 0; mt < 2; mt++) {
            int r0 = wm * 32 + mt * 16;
            a[mt][0] = xs[(r0 + g) * LD + k0 + q];
            a[mt][1] = xs[(r0 + g + 8) * LD + k0 + q];
            a[mt][2] = xs[(r0 + g) * LD + k0 + q + 4];
            a[mt][3] = xs[(r0 + g + 8) * LD + k0 + q + 4];
        }
        uint32_t b[8][2];
#pragma unroll
        for (int nt = 0; nt < 8; nt++) {
            int c0 = wn * 64 + nt * 8;
            b[nt][0] = ws[(c0 + g) * LD + k0 + q];
            b[nt][1] = ws[(c0 + g) * LD + k0 + q + 4];
        }
#pragma unroll
        for (int mt = 0; mt < 2; mt++)
#pragma unroll
            for (int nt = 0; nt < 8; nt++)
                mma8(acc[mt][nt], a[mt], b[nt]);
    }

    // epilogue: c0,c1 -> (row=g, col=2q,2q+1); c2,c3 -> row g+8
    // g_H is NPAD-padded so stores past n are harmless.
#pragma unroll
    for (int mt = 0; mt < 2; mt++) {
        int row = node0 + wm * 32 + mt * 16 + g;
#pragma unroll
        for (int nt = 0; nt < 8; nt++) {
            int col = wn * 64 + nt * 8 + q * 2;
            *(float2*)(g_H + (size_t)row * 128 + col) =
                make_float2(acc[mt][nt][0], acc[mt][nt][1]);
            *(float2*)(g_H + (size_t)(row + 8) * 128 + col) =
                make_float2(acc[mt][nt][2], acc[mt][nt][3]);
        }
    }
}

// ---- scalar GEMM (final layer): d_out = sigmoid(relu(g_AG+b)@Wfc + bfc) ----
__global__ __launch_bounds__(256)
void fc_kernel(const float* W, const float* in_bias, const float* out_bias,
               float* OUT, int n) {
    constexpr int MCOLS = 64;
    constexpr int BN = 64, BK = 64;
    constexpr int CG = MCOLS / 4;     // 16
    constexpr int NG = 256 / CG;      // 16
    constexpr int NPT = BN / NG;      // 4

    __shared__ __align__(16) float ws[BK * MCOLS];
    __shared__ __align__(16) float xs[BN * BK];

    const int tid = threadIdx.x;
    const int cg = tid % CG;
    const int ng = tid / CG;
    const int node0 = blockIdx.x * BN;

    float4 acc[NPT];
#pragma unroll
    for (int j = 0; j < NPT; j++) acc[j] = make_float4(0.f, 0.f, 0.f, 0.f);

    for (int kt = 0; kt < 128; kt += BK) {
#pragma unroll
        for (int i = tid; i < BK * MCOLS / 4; i += 256)
            ((float4*)ws)[i] = ((const float4*)(W + (size_t)kt * MCOLS))[i];
#pragma unroll
        for (int i = tid; i < BN * BK / 4; i += 256) {
            int flat = i * 4;
            int nn = flat / BK;
            int kk = flat % BK;
            float4 v = make_float4(0.f, 0.f, 0.f, 0.f);
            int gn = node0 + nn;
            if (gn < n) {
                v = *(const float4*)(g_AG + (size_t)gn * 128 + kt + kk);
                float4 bb = *(const float4*)(in_bias + kt + kk);
                v.x = fmaxf(v.x + bb.x, 0.f);
                v.y = fmaxf(v.y + bb.y, 0.f);
                v.z = fmaxf(v.z + bb.z, 0.f);
                v.w = fmaxf(v.w + bb.w, 0.f);
            }
            ((float4*)xs)[i] = v;
        }
        __syncthreads();

#pragma unroll 8
        for (int k = 0; k < BK; k++) {
            float4 wv = *(const float4*)(ws + k * MCOLS + cg * 4);
#pragma unroll
            for (int j = 0; j < NPT; j++) {
                float xv = xs[(j * NG + ng) * BK + k];
                acc[j].x = fmaf(xv, wv.x, acc[j].x);
                acc[j].y = fmaf(xv, wv.y, acc[j].y);
                acc[j].z = fmaf(xv, wv.z, acc[j].z);
                acc[j].w = fmaf(xv, wv.w, acc[j].w);
            }
        }
        __syncthreads();
    }

#pragma unroll
    for (int j = 0; j < NPT; j++) {
        int gn = node0 + j * NG + ng;
        if (gn >= n) continue;
        float4 r = acc[j];
        float4 bb = *(const float4*)(out_bias + cg * 4);
        r.x = 1.f / (1.f + expf(-(r.x + bb.x)));
        r.y = 1.f / (1.f + expf(-(r.y + bb.y)));
        r.z = 1.f / (1.f + expf(-(r.z + bb.z)));
        r.w = 1.f / (1.f + expf(-(r.w + bb.w)));
        *(float4*)(OUT + (size_t)gn * MCOLS + cg * 4) = r;
    }
}

// ---- CSR aggregation: g_AG[n] = dinv[n]^2*g_H[n] + sum_e coeff_e*g_H[src_e]
__global__ __launch_bounds__(256)
void agg_csr_kernel(int n) {
    int gid = blockIdx.x * blockDim.x + threadIdx.x;
    int node = gid >> 5;
    if (node >= n) return;
    int lane = gid & 31;

    int beg = g_rowptr[node];
    int end = g_rowptr[node + 1];

    float d = g_dinv[node];
    float s = d * d;
    float4 acc = *(const float4*)(g_H + (size_t)node * 128 + lane * 4);
    acc.x *= s; acc.y *= s; acc.z *= s; acc.w *= s;

    int j = beg;
    for (; j + 1 < end; j += 2) {
        float2 e0 = g_edge[j];
        float2 e1 = g_edge[j + 1];
        int s0 = __float_as_int(e0.x);
        int s1 = __float_as_int(e1.x);
        float4 v0 = *(const float4*)(g_H + (size_t)s0 * 128 + lane * 4);
        float4 v1 = *(const float4*)(g_H + (size_t)s1 * 128 + lane * 4);
        acc.x = fmaf(e0.y, v0.x, acc.x);
        acc.y = fmaf(e0.y, v0.y, acc.y);
        acc.z = fmaf(e0.y, v0.z, acc.z);
        acc.w = fmaf(e0.y, v0.w, acc.w);
        acc.x = fmaf(e1.y, v1.x, acc.x);
        acc.y = fmaf(e1.y, v1.y, acc.y);
        acc.z = fmaf(e1.y, v1.z, acc.z);
        acc.w = fmaf(e1.y, v1.w, acc.w);
    }
    if (j < end) {
        float2 e0 = g_edge[j];
        int s0 = __float_as_int(e0.x);
        float4 v0 = *(const float4*)(g_H + (size_t)s0 * 128 + lane * 4);
        acc.x = fmaf(e0.y, v0.x, acc.x);
        acc.y = fmaf(e0.y, v0.y, acc.y);
        acc.z = fmaf(e0.y, v0.z, acc.z);
        acc.w = fmaf(e0.y, v0.w, acc.w);
    }

    *(float4*)(g_AG + (size_t)node * 128 + lane * 4) = acc;
}

// ---- launch -------------------------------------------------------------------
extern "C" void kernel_launch(void* const* d_in, const int* in_sizes, int n_in,
                              void* d_out, int out_size) {
    const float* x   = (const float*)d_in[0];
    const void*  ei  = d_in[1];
    const float* ew  = (const float*)d_in[2];
    const float* W1  = (const float*)d_in[3];
    const float* b1  = (const float*)d_in[4];
    const float* W2  = (const float*)d_in[5];
    const float* b2  = (const float*)d_in[6];
    const float* Wfc = (const float*)d_in[7];
    const float* bfc = (const float*)d_in[8];

    int N = in_sizes[0] / 128;
    int E = in_sizes[2];

    int gb128 = (N + 127) / 128;
    int gb64 = (N + 63) / 64;
    int awarps = (N * 32 + 255) / 256;
    int eb = (E + 255) / 256;
    int nb = (N + 255) / 256;

    const int MMA_SMEM = 2 * 128 * 132 * 4;   // 135168 B
    cudaFuncSetAttribute(mma_gemm_kernel<0, false>,
                         cudaFuncAttributeMaxDynamicSharedMemorySize, MMA_SMEM);
    cudaFuncSetAttribute(mma_gemm_kernel<1, true>,
                         cudaFuncAttributeMaxDynamicSharedMemorySize, MMA_SMEM);

    // fork side stream: CSR build overlaps layer-1 GEMM
    cudaStream_t s2;
    cudaStreamCreateWithFlags(&s2, cudaStreamNonBlocking);
    cudaEvent_t evF, evJ;
    cudaEventCreateWithFlags(&evF, cudaEventDisableTiming);
    cudaEventCreateWithFlags(&evJ, cudaEventDisableTiming);

    cudaEventRecord(evF, 0);
    cudaStreamWaitEvent(s2, evF, 0);

    detect_kernel<<<1, 256, 0, s2>>>((const int*)ei, 2 * E);
    deg_init_kernel<<<nb, 256, 0, s2>>>(N);
    deg_accum_kernel<<<eb, 256, 0, s2>>>(ei, ew, E);
    deg_fin_kernel<<<nb, 256, 0, s2>>>(N);
    scan_kernel<<<1, 1024, 0, s2>>>(N);
    scatter_kernel<<<eb, 256, 0, s2>>>(ei, ew, E);
    cudaEventRecord(evJ, s2);

    // layer 1: g_H = x@W1 (tf32 warp-mma tensor cores)
    mma_gemm_kernel<0, false><<<gb128, 256, MMA_SMEM>>>(x, W1, nullptr, N);
    cudaStreamWaitEvent(0, evJ, 0);
    agg_csr_kernel<<<awarps, 256>>>(N);

    // layer 2: g_H = relu(g_AG + b1)@W2 (tf32 warp-mma tensor cores)
    mma_gemm_kernel<1, true><<<gb128, 256, MMA_SMEM>>>(nullptr, W2, b1, N);
    agg_csr_kernel<<<awarps, 256>>>(N);

    // final: d_out = sigmoid( relu(g_AG + b2) @ Wfc + bfc )  (scalar fp32)
    fc_kernel<<<gb64, 256>>>(Wfc, b2, bfc, (float*)d_out, N);
}

// round 12
// speedup vs baseline: 1.5834x; 1.3167x over previous
#include <cuda_runtime.h>
#include <cuda_bf16.h>
#include <math.h>
#include <stdint.h>

typedef unsigned long long ull;

// ---- scratch (device globals; referenced ONLY inside device code) ----------
#define NMAX 100000
#define NPAD 100096              /* 782 * 128 (mma tile padding) */
#define EMAX 1600000
__device__ __align__(16) __nv_bfloat16 g_Hb[NPAD * 128];  // H in bf16
__device__ __align__(16) float g_AG[NPAD * 128];   // aggregation result (fp32)
__device__ float  g_dinv[NMAX];                    // rsqrt(weighted degree)
__device__ int    g_cnt[NMAX];                     // in-degree counts
__device__ int    g_rowptr[NMAX + 1];              // CSR row pointers (by dst)
__device__ int    g_pos[NMAX];                     // scatter cursors
__device__ __align__(8) float2 g_edge[EMAX];       // {src_bits, coeff} by dst
__device__ int    g_is64;                          // edge_index is int64?

// ---- tf32 conversion + warp mma (plain sm_103-legal, sm_80+ PTX) -----------
__device__ __forceinline__ uint32_t f2tf(float x) {
    uint32_t r;
    asm("cvt.rna.tf32.f32 %0, %1;" : "=r"(r) : "f"(x));
    return r;
}
__device__ __forceinline__ void mma8(float* d, const uint32_t* a,
                                     const uint32_t* b) {
    asm volatile(
        "mma.sync.aligned.m16n8k8.row.col.f32.tf32.tf32.f32 "
        "{%0,%1,%2,%3}, {%4,%5,%6,%7}, {%8,%9}, {%0,%1,%2,%3};"
        : "+f"(d[0]), "+f"(d[1]), "+f"(d[2]), "+f"(d[3])
        : "r"(a[0]), "r"(a[1]), "r"(a[2]), "r"(a[3]), "r"(b[0]), "r"(b[1]));
}

// bf16 gather: 4 features (8 bytes) per lane, converted to fp32
__device__ __forceinline__ float4 ldHb4(int row, int lane) {
    uint2 u = *(const uint2*)(g_Hb + (size_t)row * 128 + lane * 4);
    __nv_bfloat162 p0 = *(__nv_bfloat162*)&u.x;
    __nv_bfloat162 p1 = *(__nv_bfloat162*)&u.y;
    float2 f0 = __bfloat1622float2(p0);
    float2 f1 = __bfloat1622float2(p1);
    return make_float4(f0.x, f0.y, f1.x, f1.y);
}

// ---- edge-index dtype detection --------------------------------------------
__global__ void detect_kernel(const int* ei32, int twoE) {
    __shared__ int any;
    if (threadIdx.x == 0) any = 0;
    __syncthreads();
    int lim = twoE < 8192 ? twoE : 8192;
    for (int i = threadIdx.x * 2 + 1; i < lim; i += 512)
        if (ei32[i] != 0) any = 1;
    __syncthreads();
    if (threadIdx.x == 0) g_is64 = (any == 0) ? 1 : 0;
}

__device__ __forceinline__ void load_edge(const void* ei, int E, int e,
                                          int& r, int& c) {
    if (g_is64) {
        const long long* p = (const long long*)ei;
        r = (int)p[e];
        c = (int)p[(size_t)E + e];
    } else {
        const int* p = (const int*)ei;
        r = p[e];
        c = p[(size_t)E + e];
    }
}

// ---- degree + histogram ------------------------------------------------------
__global__ void deg_init_kernel(int n) {
    int i = blockIdx.x * blockDim.x + threadIdx.x;
    if (i < n) { g_dinv[i] = 1.0f; g_cnt[i] = 0; }
}

__global__ void deg_accum_kernel(const void* ei, const float* w, int E) {
    int e = blockIdx.x * blockDim.x + threadIdx.x;
    if (e < E) {
        int r, c;
        load_edge(ei, E, e, r, c);
        atomicAdd(&g_dinv[c], w[e]);
        atomicAdd(&g_cnt[c], 1);
    }
}

__global__ void deg_fin_kernel(int n) {
    int i = blockIdx.x * blockDim.x + threadIdx.x;
    if (i < n) {
        float d = g_dinv[i];
        float r = rsqrtf(d);
        r = r * (1.5f - 0.5f * d * r * r);
        g_dinv[i] = r;
    }
}

// ---- single-block exclusive scan of g_cnt -> g_rowptr, g_pos ----------------
__global__ __launch_bounds__(1024)
void scan_kernel(int n) {
    __shared__ int bsum[1024];
    int t = threadIdx.x;
    int chunk = (n + 1023) / 1024;
    int s = t * chunk;
    int e = min(s + chunk, n);
    int sum = 0;
    for (int i = s; i < e; i++) sum += g_cnt[i];
    bsum[t] = sum;
    __syncthreads();
    for (int off = 1; off < 1024; off <<= 1) {
        int v = 0;
        if (t >= off) v = bsum[t - off];
        __syncthreads();
        if (t >= off) bsum[t] += v;
        __syncthreads();
    }
    int run = (t == 0) ? 0 : bsum[t - 1];
    for (int i = s; i < e; i++) {
        g_rowptr[i] = run;
        g_pos[i] = run;
        run += g_cnt[i];
    }
    if (t == 1023 || e == n) g_rowptr[n] = bsum[1023];
}

// ---- scatter edges into CSR, precompute coeff --------------------------------
__global__ void scatter_kernel(const void* ei, const float* w, int E) {
    int e = blockIdx.x * blockDim.x + threadIdx.x;
    if (e >= E) return;
    int r, c;
    load_edge(ei, E, e, r, c);
    float coeff = g_dinv[r] * __ldg(&w[e]) * g_dinv[c];
    int p = atomicAdd(&g_pos[c], 1);
    g_edge[p] = make_float2(__int_as_float(r), coeff);
}

// ==== warp-MMA tf32 GEMM: g_Hb[128-tile] = f(X)[128,128] @ W[128,128] =======
// block 256 thr / 8 warps; warp tile 32(M)x64(N); m16n8k8; BK=64 two-pass
// staging (smem 69.6KB -> 2 CTAs/SM). LD=68 keeps fragment LDS conflict-free.
// Output stored as bf16 (feeds the L2-resident aggregation gathers).
template <int XSEL, bool IN_RELU>
__global__ __launch_bounds__(256, 2)
void mma_gemm_kernel(const float* Xarg, const float* W,
                     const float* in_bias, int n) {
    constexpr int LD = 68;
    extern __shared__ __align__(16) uint32_t smem[];
    uint32_t* xs = smem;               // [128 rows][LD k]
    uint32_t* ws = smem + 128 * LD;    // [128 cols][LD k]

    const float* X = (XSEL == 0) ? Xarg : g_AG;

    const int tid = threadIdx.x;
    const int node0 = blockIdx.x * 128;

    const int wid = tid >> 5;
    const int lane = tid & 31;
    const int g = lane >> 2;     // groupID (0..7)
    const int q = lane & 3;      // threadID_in_group (0..3)
    const int wm = wid & 3;      // warp M index: rows wm*32..+31
    const int wn = wid >> 2;     // warp N index: cols wn*64..+63

    float acc[2][8][4];
#pragma unroll
    for (int mt = 0; mt < 2; mt++)
#pragma unroll
        for (int nt = 0; nt < 8; nt++)
#pragma unroll
            for (int r = 0; r < 4; r++) acc[mt][nt][r] = 0.f;

    for (int kt = 0; kt < 128; kt += 64) {
        // stage X chunk: 128 rows x 16 float4 (relu+bias fused, tf32)
        for (int i = tid; i < 128 * 16; i += 256) {
            int row = i >> 4;
            int k4 = (i & 15) * 4;
            float4 v = make_float4(0.f, 0.f, 0.f, 0.f);
            int gn = node0 + row;
            if (gn < n) {
                v = *(const float4*)(X + (size_t)gn * 128 + kt + k4);
                if (IN_RELU) {
                    float4 bb = *(const float4*)(in_bias + kt + k4);
                    v.x = fmaxf(v.x + bb.x, 0.f);
                    v.y = fmaxf(v.y + bb.y, 0.f);
                    v.z = fmaxf(v.z + bb.z, 0.f);
                    v.w = fmaxf(v.w + bb.w, 0.f);
                }
            }
            uint4 t = make_uint4(f2tf(v.x), f2tf(v.y), f2tf(v.z), f2tf(v.w));
            *(uint4*)(xs + row * LD + k4) = t;
        }
        // stage W chunk transposed: ws[c][k] = W[kt+k][c]
        for (int i = tid; i < 16 * 128; i += 256) {
            int kq = i >> 7;        // 0..15
            int c = i & 127;
#pragma unroll
            for (int j = 0; j < 4; j++) {
                int k = kq * 4 + j;
                ws[c * LD + k] = f2tf(W[(size_t)(kt + k) * 128 + c]);
            }
        }
        __syncthreads();

#pragma unroll 1
        for (int k0 = 0; k0 < 64; k0 += 8) {
            uint32_t a[2][4];
#pragma unroll
            for (int mt = 0; mt < 2; mt++) {
                int r0 = wm * 32 + mt * 16;
                a[mt][0] = xs[(r0 + g) * LD + k0 + q];
                a[mt][1] = xs[(r0 + g + 8) * LD + k0 + q];
                a[mt][2] = xs[(r0 + g) * LD + k0 + q + 4];
                a[mt][3] = xs[(r0 + g + 8) * LD + k0 + q + 4];
            }
            uint32_t b[8][2];
#pragma unroll
            for (int nt = 0; nt < 8; nt++) {
                int c0 = wn * 64 + nt * 8;
                b[nt][0] = ws[(c0 + g) * LD + k0 + q];
                b[nt][1] = ws[(c0 + g) * LD + k0 + q + 4];
            }
#pragma unroll
            for (int mt = 0; mt < 2; mt++)
#pragma unroll
                for (int nt = 0; nt < 8; nt++)
                    mma8(acc[mt][nt], a[mt], b[nt]);
        }
        __syncthreads();
    }

    // epilogue: store bf16 pairs; NPAD padding makes tail stores harmless
#pragma unroll
    for (int mt = 0; mt < 2; mt++) {
        int row = node0 + wm * 32 + mt * 16 + g;
#pragma unroll
        for (int nt = 0; nt < 8; nt++) {
            int col = wn * 64 + nt * 8 + q * 2;
            *(__nv_bfloat162*)(g_Hb + (size_t)row * 128 + col) =
                __floats2bfloat162_rn(acc[mt][nt][0], acc[mt][nt][1]);
            *(__nv_bfloat162*)(g_Hb + (size_t)(row + 8) * 128 + col) =
                __floats2bfloat162_rn(acc[mt][nt][2], acc[mt][nt][3]);
        }
    }
}

// ---- scalar GEMM (final layer): d_out = sigmoid(relu(g_AG+b)@Wfc + bfc) ----
__global__ __launch_bounds__(256)
void fc_kernel(const float* W, const float* in_bias, const float* out_bias,
               float* OUT, int n) {
    constexpr int MCOLS = 64;
    constexpr int BN = 64, BK = 64;
    constexpr int CG = MCOLS / 4;     // 16
    constexpr int NG = 256 / CG;      // 16
    constexpr int NPT = BN / NG;      // 4

    __shared__ __align__(16) float ws[BK * MCOLS];
    __shared__ __align__(16) float xs[BN * BK];

    const int tid = threadIdx.x;
    const int cg = tid % CG;
    const int ng = tid / CG;
    const int node0 = blockIdx.x * BN;

    float4 acc[NPT];
#pragma unroll
    for (int j = 0; j < NPT; j++) acc[j] = make_float4(0.f, 0.f, 0.f, 0.f);

    for (int kt = 0; kt < 128; kt += BK) {
#pragma unroll
        for (int i = tid; i < BK * MCOLS / 4; i += 256)
            ((float4*)ws)[i] = ((const float4*)(W + (size_t)kt * MCOLS))[i];
#pragma unroll
        for (int i = tid; i < BN * BK / 4; i += 256) {
            int flat = i * 4;
            int nn = flat / BK;
            int kk = flat % BK;
            float4 v = make_float4(0.f, 0.f, 0.f, 0.f);
            int gn = node0 + nn;
            if (gn < n) {
                v = *(const float4*)(g_AG + (size_t)gn * 128 + kt + kk);
                float4 bb = *(const float4*)(in_bias + kt + kk);
                v.x = fmaxf(v.x + bb.x, 0.f);
                v.y = fmaxf(v.y + bb.y, 0.f);
                v.z = fmaxf(v.z + bb.z, 0.f);
                v.w = fmaxf(v.w + bb.w, 0.f);
            }
            ((float4*)xs)[i] = v;
        }
        __syncthreads();

#pragma unroll 8
        for (int k = 0; k < BK; k++) {
            float4 wv = *(const float4*)(ws + k * MCOLS + cg * 4);
#pragma unroll
            for (int j = 0; j < NPT; j++) {
                float xv = xs[(j * NG + ng) * BK + k];
                acc[j].x = fmaf(xv, wv.x, acc[j].x);
                acc[j].y = fmaf(xv, wv.y, acc[j].y);
                acc[j].z = fmaf(xv, wv.z, acc[j].z);
                acc[j].w = fmaf(xv, wv.w, acc[j].w);
            }
        }
        __syncthreads();
    }

#pragma unroll
    for (int j = 0; j < NPT; j++) {
        int gn = node0 + j * NG + ng;
        if (gn >= n) continue;
        float4 r = acc[j];
        float4 bb = *(const float4*)(out_bias + cg * 4);
        r.x = 1.f / (1.f + expf(-(r.x + bb.x)));
        r.y = 1.f / (1.f + expf(-(r.y + bb.y)));
        r.z = 1.f / (1.f + expf(-(r.z + bb.z)));
        r.w = 1.f / (1.f + expf(-(r.w + bb.w)));
        *(float4*)(OUT + (size_t)gn * MCOLS + cg * 4) = r;
    }
}

// ---- CSR aggregation (bf16 gathers, fp32 accumulate) ------------------------
// g_AG[n] = dinv[n]^2 * Hb[n] + sum_e coeff_e * Hb[src_e]
__global__ __launch_bounds__(256)
void agg_csr_kernel(int n) {
    int gid = blockIdx.x * blockDim.x + threadIdx.x;
    int node = gid >> 5;
    if (node >= n) return;
    int lane = gid & 31;

    int beg = g_rowptr[node];
    int end = g_rowptr[node + 1];

    float d = g_dinv[node];
    float s = d * d;
    float4 acc = ldHb4(node, lane);
    acc.x *= s; acc.y *= s; acc.z *= s; acc.w *= s;

    int j = beg;
    for (; j + 1 < end; j += 2) {
        float2 e0 = g_edge[j];
        float2 e1 = g_edge[j + 1];
        float4 v0 = ldHb4(__float_as_int(e0.x), lane);
        float4 v1 = ldHb4(__float_as_int(e1.x), lane);
        acc.x = fmaf(e0.y, v0.x, acc.x);
        acc.y = fmaf(e0.y, v0.y, acc.y);
        acc.z = fmaf(e0.y, v0.z, acc.z);
        acc.w = fmaf(e0.y, v0.w, acc.w);
        acc.x = fmaf(e1.y, v1.x, acc.x);
        acc.y = fmaf(e1.y, v1.y, acc.y);
        acc.z = fmaf(e1.y, v1.z, acc.z);
        acc.w = fmaf(e1.y, v1.w, acc.w);
    }
    if (j < end) {
        float2 e0 = g_edge[j];
        float4 v0 = ldHb4(__float_as_int(e0.x), lane);
        acc.x = fmaf(e0.y, v0.x, acc.x);
        acc.y = fmaf(e0.y, v0.y, acc.y);
        acc.z = fmaf(e0.y, v0.z, acc.z);
        acc.w = fmaf(e0.y, v0.w, acc.w);
    }

    *(float4*)(g_AG + (size_t)node * 128 + lane * 4) = acc;
}

// ---- launch -------------------------------------------------------------------
extern "C" void kernel_launch(void* const* d_in, const int* in_sizes, int n_in,
                              void* d_out, int out_size) {
    const float* x   = (const float*)d_in[0];
    const void*  ei  = d_in[1];
    const float* ew  = (const float*)d_in[2];
    const float* W1  = (const float*)d_in[3];
    const float* b1  = (const float*)d_in[4];
    const float* W2  = (const float*)d_in[5];
    const float* b2  = (const float*)d_in[6];
    const float* Wfc = (const float*)d_in[7];
    const float* bfc = (const float*)d_in[8];

    int N = in_sizes[0] / 128;
    int E = in_sizes[2];

    int gb128 = (N + 127) / 128;
    int gb64 = (N + 63) / 64;
    int awarps = (N * 32 + 255) / 256;
    int eb = (E + 255) / 256;
    int nb = (N + 255) / 256;

    const int MMA_SMEM = 2 * 128 * 68 * 4;   // 69632 B -> 2 CTAs/SM
    cudaFuncSetAttribute(mma_gemm_kernel<0, false>,
                         cudaFuncAttributeMaxDynamicSharedMemorySize, MMA_SMEM);
    cudaFuncSetAttribute(mma_gemm_kernel<1, true>,
                         cudaFuncAttributeMaxDynamicSharedMemorySize, MMA_SMEM);

    // fork side stream: CSR build overlaps layer-1 GEMM
    cudaStream_t s2;
    cudaStreamCreateWithFlags(&s2, cudaStreamNonBlocking);
    cudaEvent_t evF, evJ;
    cudaEventCreateWithFlags(&evF, cudaEventDisableTiming);
    cudaEventCreateWithFlags(&evJ, cudaEventDisableTiming);

    cudaEventRecord(evF, 0);
    cudaStreamWaitEvent(s2, evF, 0);

    detect_kernel<<<1, 256, 0, s2>>>((const int*)ei, 2 * E);
    deg_init_kernel<<<nb, 256, 0, s2>>>(N);
    deg_accum_kernel<<<eb, 256, 0, s2>>>(ei, ew, E);
    deg_fin_kernel<<<nb, 256, 0, s2>>>(N);
    scan_kernel<<<1, 1024, 0, s2>>>(N);
    scatter_kernel<<<eb, 256, 0, s2>>>(ei, ew, E);
    cudaEventRecord(evJ, s2);

    // layer 1: Hb = x@W1 (tf32 warp-mma, bf16 output)
    mma_gemm_kernel<0, false><<<gb128, 256, MMA_SMEM>>>(x, W1, nullptr, N);
    cudaStreamWaitEvent(0, evJ, 0);
    agg_csr_kernel<<<awarps, 256>>>(N);

    // layer 2: Hb = relu(g_AG + b1)@W2 (tf32 warp-mma, bf16 output)
    mma_gemm_kernel<1, true><<<gb128, 256, MMA_SMEM>>>(nullptr, W2, b1, N);
    agg_csr_kernel<<<awarps, 256>>>(N);

    // final: d_out = sigmoid( relu(g_AG + b2) @ Wfc + bfc )  (scalar fp32)
    fc_kernel<<<gb64, 256>>>(Wfc, b2, bfc, (float*)d_out, N);
}

// round 13
// speedup vs baseline: 1.6909x; 1.0679x over previous
#include <cuda_runtime.h>
#include <cuda_bf16.h>
#include <math.h>
#include <stdint.h>

typedef unsigned long long ull;

// ---- scratch (device globals; referenced ONLY inside device code) ----------
#define NMAX 100000
#define NPAD 100096              /* 782 * 128 (mma tile padding) */
#define EMAX 1600000
__device__ __align__(16) __nv_bfloat16 g_Hb[NPAD * 128];  // H in bf16
__device__ __align__(16) float g_AG[NPAD * 128];   // aggregation result (fp32)
__device__ float  g_dinv[NMAX];                    // rsqrt(weighted degree)
__device__ int    g_cnt[NMAX];                     // in-degree counts
__device__ int    g_rowptr[NMAX + 1];              // CSR row pointers (by dst)
__device__ int    g_pos[NMAX];                     // scatter cursors
__device__ __align__(16) float2 g_edge[EMAX];      // {src_bits, coeff} by dst
__device__ int    g_is64;                          // edge_index is int64?

// ---- tf32 conversion + warp mma (plain sm_103-legal, sm_80+ PTX) -----------
__device__ __forceinline__ uint32_t f2tf(float x) {
    uint32_t r;
    asm("cvt.rna.tf32.f32 %0, %1;" : "=r"(r) : "f"(x));
    return r;
}
__device__ __forceinline__ void mma8(float* d, const uint32_t* a,
                                     const uint32_t* b) {
    asm volatile(
        "mma.sync.aligned.m16n8k8.row.col.f32.tf32.tf32.f32 "
        "{%0,%1,%2,%3}, {%4,%5,%6,%7}, {%8,%9}, {%0,%1,%2,%3};"
        : "+f"(d[0]), "+f"(d[1]), "+f"(d[2]), "+f"(d[3])
        : "r"(a[0]), "r"(a[1]), "r"(a[2]), "r"(a[3]), "r"(b[0]), "r"(b[1]));
}

// bf16 gather: 4 features (8 bytes) per lane, converted to fp32
__device__ __forceinline__ float4 ldHb4(int row, int lane) {
    uint2 u = *(const uint2*)(g_Hb + (size_t)row * 128 + lane * 4);
    __nv_bfloat162 p0 = *(__nv_bfloat162*)&u.x;
    __nv_bfloat162 p1 = *(__nv_bfloat162*)&u.y;
    float2 f0 = __bfloat1622float2(p0);
    float2 f1 = __bfloat1622float2(p1);
    return make_float4(f0.x, f0.y, f1.x, f1.y);
}
__device__ __forceinline__ void fma4(float4& acc, float c, const float4& v) {
    acc.x = fmaf(c, v.x, acc.x);
    acc.y = fmaf(c, v.y, acc.y);
    acc.z = fmaf(c, v.z, acc.z);
    acc.w = fmaf(c, v.w, acc.w);
}

// ---- edge-index dtype detection --------------------------------------------
__global__ void detect_kernel(const int* ei32, int twoE) {
    __shared__ int any;
    if (threadIdx.x == 0) any = 0;
    __syncthreads();
    int lim = twoE < 8192 ? twoE : 8192;
    for (int i = threadIdx.x * 2 + 1; i < lim; i += 512)
        if (ei32[i] != 0) any = 1;
    __syncthreads();
    if (threadIdx.x == 0) g_is64 = (any == 0) ? 1 : 0;
}

__device__ __forceinline__ void load_edge(const void* ei, int E, int e,
                                          int& r, int& c) {
    if (g_is64) {
        const long long* p = (const long long*)ei;
        r = (int)p[e];
        c = (int)p[(size_t)E + e];
    } else {
        const int* p = (const int*)ei;
        r = p[e];
        c = p[(size_t)E + e];
    }
}

// ---- degree + histogram ------------------------------------------------------
__global__ void deg_init_kernel(int n) {
    int i = blockIdx.x * blockDim.x + threadIdx.x;
    if (i < n) { g_dinv[i] = 1.0f; g_cnt[i] = 0; }
}

__global__ void deg_accum_kernel(const void* ei, const float* w, int E) {
    int e = blockIdx.x * blockDim.x + threadIdx.x;
    if (e < E) {
        int r, c;
        load_edge(ei, E, e, r, c);
        atomicAdd(&g_dinv[c], w[e]);
        atomicAdd(&g_cnt[c], 1);
    }
}

__global__ void deg_fin_kernel(int n) {
    int i = blockIdx.x * blockDim.x + threadIdx.x;
    if (i < n) {
        float d = g_dinv[i];
        float r = rsqrtf(d);
        r = r * (1.5f - 0.5f * d * r * r);
        g_dinv[i] = r;
    }
}

// ---- single-block exclusive scan of g_cnt -> g_rowptr, g_pos ----------------
__global__ __launch_bounds__(1024)
void scan_kernel(int n) {
    __shared__ int bsum[1024];
    int t = threadIdx.x;
    int chunk = (n + 1023) / 1024;
    int s = t * chunk;
    int e = min(s + chunk, n);
    int sum = 0;
    for (int i = s; i < e; i++) sum += g_cnt[i];
    bsum[t] = sum;
    __syncthreads();
    for (int off = 1; off < 1024; off <<= 1) {
        int v = 0;
        if (t >= off) v = bsum[t - off];
        __syncthreads();
        if (t >= off) bsum[t] += v;
        __syncthreads();
    }
    int run = (t == 0) ? 0 : bsum[t - 1];
    for (int i = s; i < e; i++) {
        g_rowptr[i] = run;
        g_pos[i] = run;
        run += g_cnt[i];
    }
    if (t == 1023 || e == n) g_rowptr[n] = bsum[1023];
}

// ---- scatter edges into CSR, precompute coeff --------------------------------
__global__ void scatter_kernel(const void* ei, const float* w, int E) {
    int e = blockIdx.x * blockDim.x + threadIdx.x;
    if (e >= E) return;
    int r, c;
    load_edge(ei, E, e, r, c);
    float coeff = g_dinv[r] * __ldg(&w[e]) * g_dinv[c];
    int p = atomicAdd(&g_pos[c], 1);
    g_edge[p] = make_float2(__int_as_float(r), coeff);
}

// ==== warp-MMA tf32 GEMM: g_Hb[128-tile] = f(X)[128,128] @ W[128,128] =======
// block 256 thr / 8 warps; warp tile 32(M)x64(N); m16n8k8; BK=64 two-pass
// staging (2 CTAs/SM). LD=68 keeps fragment LDS conflict-free. bf16 output.
template <int XSEL, bool IN_RELU>
__global__ __launch_bounds__(256, 2)
void mma_gemm_kernel(const float* Xarg, const float* W,
                     const float* in_bias, int n) {
    constexpr int LD = 68;
    extern __shared__ __align__(16) uint32_t smem[];
    uint32_t* xs = smem;               // [128 rows][LD k]
    uint32_t* ws = smem + 128 * LD;    // [128 cols][LD k]

    const float* X = (XSEL == 0) ? Xarg : g_AG;

    const int tid = threadIdx.x;
    const int node0 = blockIdx.x * 128;

    const int wid = tid >> 5;
    const int lane = tid & 31;
    const int g = lane >> 2;
    const int q = lane & 3;
    const int wm = wid & 3;
    const int wn = wid >> 2;

    float acc[2][8][4];
#pragma unroll
    for (int mt = 0; mt < 2; mt++)
#pragma unroll
        for (int nt = 0; nt < 8; nt++)
#pragma unroll
            for (int r = 0; r < 4; r++) acc[mt][nt][r] = 0.f;

    for (int kt = 0; kt < 128; kt += 64) {
        for (int i = tid; i < 128 * 16; i += 256) {
            int row = i >> 4;
            int k4 = (i & 15) * 4;
            float4 v = make_float4(0.f, 0.f, 0.f, 0.f);
            int gn = node0 + row;
            if (gn < n) {
                v = *(const float4*)(X + (size_t)gn * 128 + kt + k4);
                if (IN_RELU) {
                    float4 bb = *(const float4*)(in_bias + kt + k4);
                    v.x = fmaxf(v.x + bb.x, 0.f);
                    v.y = fmaxf(v.y + bb.y, 0.f);
                    v.z = fmaxf(v.z + bb.z, 0.f);
                    v.w = fmaxf(v.w + bb.w, 0.f);
                }
            }
            uint4 t = make_uint4(f2tf(v.x), f2tf(v.y), f2tf(v.z), f2tf(v.w));
            *(uint4*)(xs + row * LD + k4) = t;
        }
        for (int i = tid; i < 16 * 128; i += 256) {
            int kq = i >> 7;
            int c = i & 127;
#pragma unroll
            for (int j = 0; j < 4; j++) {
                int k = kq * 4 + j;
                ws[c * LD + k] = f2tf(W[(size_t)(kt + k) * 128 + c]);
            }
        }
        __syncthreads();

#pragma unroll 1
        for (int k0 = 0; k0 < 64; k0 += 8) {
            uint32_t a[2][4];
#pragma unroll
            for (int mt = 0; mt < 2; mt++) {
                int r0 = wm * 32 + mt * 16;
                a[mt][0] = xs[(r0 + g) * LD + k0 + q];
                a[mt][1] = xs[(r0 + g + 8) * LD + k0 + q];
                a[mt][2] = xs[(r0 + g) * LD + k0 + q + 4];
                a[mt][3] = xs[(r0 + g + 8) * LD + k0 + q + 4];
            }
            uint32_t b[8][2];
#pragma unroll
            for (int nt = 0; nt < 8; nt++) {
                int c0 = wn * 64 + nt * 8;
                b[nt][0] = ws[(c0 + g) * LD + k0 + q];
                b[nt][1] = ws[(c0 + g) * LD + k0 + q + 4];
            }
#pragma unroll
            for (int mt = 0; mt < 2; mt++)
#pragma unroll
                for (int nt = 0; nt < 8; nt++)
                    mma8(acc[mt][nt], a[mt], b[nt]);
        }
        __syncthreads();
    }

#pragma unroll
    for (int mt = 0; mt < 2; mt++) {
        int row = node0 + wm * 32 + mt * 16 + g;
#pragma unroll
        for (int nt = 0; nt < 8; nt++) {
            int col = wn * 64 + nt * 8 + q * 2;
            *(__nv_bfloat162*)(g_Hb + (size_t)row * 128 + col) =
                __floats2bfloat162_rn(acc[mt][nt][0], acc[mt][nt][1]);
            *(__nv_bfloat162*)(g_Hb + (size_t)(row + 8) * 128 + col) =
                __floats2bfloat162_rn(acc[mt][nt][2], acc[mt][nt][3]);
        }
    }
}

// ==== warp-MMA tf32 fc: d_out = sigmoid(relu(g_AG+b2)[N,128]@Wfc[128,64]+bfc)
// tile M=128 x N=64; 8 warps = 4M x 2N; warp tile 32x32 (2x4 fragments).
__global__ __launch_bounds__(256, 2)
void fc_mma_kernel(const float* W, const float* in_bias,
                   const float* out_bias, float* OUT, int n) {
    constexpr int LD = 68;
    extern __shared__ __align__(16) uint32_t smem[];
    uint32_t* xs = smem;               // [128 rows][LD k]
    uint32_t* ws = smem + 128 * LD;    // [64 cols][LD k]

    const int tid = threadIdx.x;
    const int node0 = blockIdx.x * 128;

    const int wid = tid >> 5;
    const int lane = tid & 31;
    const int g = lane >> 2;
    const int q = lane & 3;
    const int wm = wid & 3;      // rows wm*32..+31
    const int wn = wid >> 2;     // cols wn*32..+31

    float acc[2][4][4];
#pragma unroll
    for (int mt = 0; mt < 2; mt++)
#pragma unroll
        for (int nt = 0; nt < 4; nt++)
#pragma unroll
            for (int r = 0; r < 4; r++) acc[mt][nt][r] = 0.f;

    for (int kt = 0; kt < 128; kt += 64) {
        // stage X = relu(g_AG + b2), tf32
        for (int i = tid; i < 128 * 16; i += 256) {
            int row = i >> 4;
            int k4 = (i & 15) * 4;
            float4 v = make_float4(0.f, 0.f, 0.f, 0.f);
            int gn = node0 + row;
            if (gn < n) {
                v = *(const float4*)(g_AG + (size_t)gn * 128 + kt + k4);
                float4 bb = *(const float4*)(in_bias + kt + k4);
                v.x = fmaxf(v.x + bb.x, 0.f);
                v.y = fmaxf(v.y + bb.y, 0.f);
                v.z = fmaxf(v.z + bb.z, 0.f);
                v.w = fmaxf(v.w + bb.w, 0.f);
            }
            uint4 t = make_uint4(f2tf(v.x), f2tf(v.y), f2tf(v.z), f2tf(v.w));
            *(uint4*)(xs + row * LD + k4) = t;
        }
        // stage Wfc transposed: ws[c][k] = Wfc[kt+k][c], c in [0,64)
        for (int i = tid; i < 16 * 64; i += 256) {
            int kq = i >> 6;
            int c = i & 63;
#pragma unroll
            for (int j = 0; j < 4; j++) {
                int k = kq * 4 + j;
                ws[c * LD + k] = f2tf(W[(size_t)(kt + k) * 64 + c]);
            }
        }
        __syncthreads();

#pragma unroll 1
        for (int k0 = 0; k0 < 64; k0 += 8) {
            uint32_t a[2][4];
#pragma unroll
            for (int mt = 0; mt < 2; mt++) {
                int r0 = wm * 32 + mt * 16;
                a[mt][0] = xs[(r0 + g) * LD + k0 + q];
                a[mt][1] = xs[(r0 + g + 8) * LD + k0 + q];
                a[mt][2] = xs[(r0 + g) * LD + k0 + q + 4];
                a[mt][3] = xs[(r0 + g + 8) * LD + k0 + q + 4];
            }
            uint32_t b[4][2];
#pragma unroll
            for (int nt = 0; nt < 4; nt++) {
                int c0 = wn * 32 + nt * 8;
                b[nt][0] = ws[(c0 + g) * LD + k0 + q];
                b[nt][1] = ws[(c0 + g) * LD + k0 + q + 4];
            }
#pragma unroll
            for (int mt = 0; mt < 2; mt++)
#pragma unroll
                for (int nt = 0; nt < 4; nt++)
                    mma8(acc[mt][nt], a[mt], b[nt]);
        }
        __syncthreads();
    }

    // epilogue: +bfc, sigmoid, guarded fp32 stores (d_out unpadded)
#pragma unroll
    for (int mt = 0; mt < 2; mt++) {
        int row0 = node0 + wm * 32 + mt * 16 + g;
#pragma unroll
        for (int nt = 0; nt < 4; nt++) {
            int col = wn * 32 + nt * 8 + q * 2;
            float b0 = out_bias[col];
            float b1 = out_bias[col + 1];
            if (row0 < n) {
                float v0 = 1.f / (1.f + expf(-(acc[mt][nt][0] + b0)));
                float v1 = 1.f / (1.f + expf(-(acc[mt][nt][1] + b1)));
                *(float2*)(OUT + (size_t)row0 * 64 + col) = make_float2(v0, v1);
            }
            if (row0 + 8 < n) {
                float v2 = 1.f / (1.f + expf(-(acc[mt][nt][2] + b0)));
                float v3 = 1.f / (1.f + expf(-(acc[mt][nt][3] + b1)));
                *(float2*)(OUT + (size_t)(row0 + 8) * 64 + col) =
                    make_float2(v2, v3);
            }
        }
    }
}

// ---- CSR aggregation (bf16 gathers, fp32 accumulate, 4-edge MLP) -----------
__global__ __launch_bounds__(256)
void agg_csr_kernel(int n) {
    int gid = blockIdx.x * blockDim.x + threadIdx.x;
    int node = gid >> 5;
    if (node >= n) return;
    int lane = gid & 31;

    int beg = g_rowptr[node];
    int end = g_rowptr[node + 1];

    float d = g_dinv[node];
    float s = d * d;
    float4 acc = ldHb4(node, lane);
    acc.x *= s; acc.y *= s; acc.z *= s; acc.w *= s;

    int j = beg;
    for (; j + 3 < end; j += 4) {
        float2 e0 = g_edge[j];
        float2 e1 = g_edge[j + 1];
        float2 e2 = g_edge[j + 2];
        float2 e3 = g_edge[j + 3];
        float4 v0 = ldHb4(__float_as_int(e0.x), lane);
        float4 v1 = ldHb4(__float_as_int(e1.x), lane);
        float4 v2 = ldHb4(__float_as_int(e2.x), lane);
        float4 v3 = ldHb4(__float_as_int(e3.x), lane);
        fma4(acc, e0.y, v0);
        fma4(acc, e1.y, v1);
        fma4(acc, e2.y, v2);
        fma4(acc, e3.y, v3);
    }
    for (; j < end; j++) {
        float2 e0 = g_edge[j];
        float4 v0 = ldHb4(__float_as_int(e0.x), lane);
        fma4(acc, e0.y, v0);
    }

    *(float4*)(g_AG + (size_t)node * 128 + lane * 4) = acc;
}

// ---- launch -------------------------------------------------------------------
extern "C" void kernel_launch(void* const* d_in, const int* in_sizes, int n_in,
                              void* d_out, int out_size) {
    const float* x   = (const float*)d_in[0];
    const void*  ei  = d_in[1];
    const float* ew  = (const float*)d_in[2];
    const float* W1  = (const float*)d_in[3];
    const float* b1  = (const float*)d_in[4];
    const float* W2  = (const float*)d_in[5];
    const float* b2  = (const float*)d_in[6];
    const float* Wfc = (const float*)d_in[7];
    const float* bfc = (const float*)d_in[8];

    int N = in_sizes[0] / 128;
    int E = in_sizes[2];

    int gb128 = (N + 127) / 128;
    int awarps = (N * 32 + 255) / 256;
    int eb = (E + 255) / 256;
    int nb = (N + 255) / 256;

    const int MMA_SMEM = 2 * 128 * 68 * 4;        // 69632 B
    const int FC_SMEM = (128 + 64) * 68 * 4;      // 52224 B
    cudaFuncSetAttribute(mma_gemm_kernel<0, false>,
                         cudaFuncAttributeMaxDynamicSharedMemorySize, MMA_SMEM);
    cudaFuncSetAttribute(mma_gemm_kernel<1, true>,
                         cudaFuncAttributeMaxDynamicSharedMemorySize, MMA_SMEM);
    cudaFuncSetAttribute(fc_mma_kernel,
                         cudaFuncAttributeMaxDynamicSharedMemorySize, FC_SMEM);

    // fork side stream: CSR build overlaps layer-1 GEMM
    cudaStream_t s2;
    cudaStreamCreateWithFlags(&s2, cudaStreamNonBlocking);
    cudaEvent_t evF, evJ;
    cudaEventCreateWithFlags(&evF, cudaEventDisableTiming);
    cudaEventCreateWithFlags(&evJ, cudaEventDisableTiming);

    cudaEventRecord(evF, 0);
    cudaStreamWaitEvent(s2, evF, 0);

    detect_kernel<<<1, 256, 0, s2>>>((const int*)ei, 2 * E);
    deg_init_kernel<<<nb, 256, 0, s2>>>(N);
    deg_accum_kernel<<<eb, 256, 0, s2>>>(ei, ew, E);
    deg_fin_kernel<<<nb, 256, 0, s2>>>(N);
    scan_kernel<<<1, 1024, 0, s2>>>(N);
    scatter_kernel<<<eb, 256, 0, s2>>>(ei, ew, E);
    cudaEventRecord(evJ, s2);

    // layer 1: Hb = x@W1 (tf32 warp-mma, bf16 output)
    mma_gemm_kernel<0, false><<<gb128, 256, MMA_SMEM>>>(x, W1, nullptr, N);
    cudaStreamWaitEvent(0, evJ, 0);
    agg_csr_kernel<<<awarps, 256>>>(N);

    // layer 2: Hb = relu(g_AG + b1)@W2 (tf32 warp-mma, bf16 output)
    mma_gemm_kernel<1, true><<<gb128, 256, MMA_SMEM>>>(nullptr, W2, b1, N);
    agg_csr_kernel<<<awarps, 256>>>(N);

    // final: d_out = sigmoid( relu(g_AG + b2) @ Wfc + bfc )  (tf32 warp-mma)
    fc_mma_kernel<<<gb128, 256, FC_SMEM>>>(Wfc, b2, bfc, (float*)d_out, N);
}